// round 7
// baseline (speedup 1.0000x reference)
#include <cuda_runtime.h>
#include <cuda_bf16.h>

#define NN 262144
#define BB 4096
#define NEGV -1000000000.0f

__device__ int g_starts[BB + 1];
__device__ float g_gb[BB * 64];   // precomputed glob@W1b + b1

// ---- fused prep: blocks [0,512) compute gb; blocks [512,768) compute seg starts ----
__global__ void __launch_bounds__(256) prep_kernel(
    const int* __restrict__ batch,
    const float* __restrict__ glob, const float* __restrict__ W1,
    const float* __restrict__ b1)
{
    const int tid = threadIdx.x, w = tid >> 5, lane = tid & 31;
    if (blockIdx.x < 512) {
        // gb[b][j] = glob[b] @ W1[128:][:,j] + b1[j]
        __shared__ float sW1b[8192];
        {
            const float4* src = (const float4*)(W1 + 128 * 64);
            float4* dst = (float4*)sW1b;
            #pragma unroll
            for (int i = 0; i < 8; ++i) dst[tid + 256 * i] = src[tid + 256 * i];
        }
        const int b = blockIdx.x * 8 + w;
        float gl[4];
        #pragma unroll
        for (int i = 0; i < 4; ++i) gl[i] = glob[b * 128 + lane + 32 * i];
        float2 bv = *(const float2*)&b1[2 * lane];
        float g0 = bv.x, g1 = bv.y;
        __syncthreads();
        #pragma unroll 8
        for (int k = 0; k < 128; ++k) {
            float x = __shfl_sync(0xffffffffu, gl[k >> 5], k & 31);
            float2 wv = *(const float2*)&sW1b[k * 64 + 2 * lane];
            g0 = fmaf(x, wv.x, g0);
            g1 = fmaf(x, wv.y, g1);
        }
        *(float2*)&g_gb[b * 64 + 2 * lane] = make_float2(g0, g1);
    } else {
        // segment starts, 4 elements per thread (int4)
        const int sid = blockIdx.x - 512;          // 0..255
        const int i0 = sid * 1024 + tid * 4;
        int4 v = *(const int4*)&batch[i0];
        int prev = __shfl_up_sync(0xffffffffu, v.w, 1);
        if (lane == 0) prev = (i0 == 0) ? -1 : batch[i0 - 1];
        int c[4] = {v.x, v.y, v.z, v.w};
        int p = prev;
        #pragma unroll
        for (int t = 0; t < 4; ++t) {
            for (int b = p + 1; b <= c[t]; ++b) g_starts[b] = i0 + t;
            p = c[t];
        }
        if (i0 + 4 == NN) {
            for (int b = v.w + 1; b <= BB; ++b) g_starts[b] = NN;
        }
    }
}

// ---- packed f32x2 helpers ----
__device__ __forceinline__ unsigned long long pk2(float a, float b) {
    unsigned long long r;
    asm("mov.b64 %0, {%1, %2};" : "=l"(r) : "f"(a), "f"(b));
    return r;
}
__device__ __forceinline__ void upk2(unsigned long long v, float& a, float& b) {
    asm("mov.b64 {%0, %1}, %2;" : "=f"(a), "=f"(b) : "l"(v));
}
__device__ __forceinline__ unsigned long long fma2(unsigned long long a,
                                                   unsigned long long b,
                                                   unsigned long long c) {
    unsigned long long r;
    asm("fma.rn.f32x2 %0, %1, %2, %3;" : "=l"(r) : "l"(a), "l"(b), "l"(c));
    return r;
}

// Shared layout (floats):
//   [0, 8192)        W1 rows 0..127 (32KB)
//   [8192 + w*2560)  per-warp xp: k-major, stride 20 floats per k
//                    (16 data = 8 node-pairs across 2 batches, 4 pad);
//                    reused post-mainloop as h (16 nodes x stride 66)
#define SW1_OFF   0
#define XP_OFF    8192
#define XP_STRIDE 2560
#define SMEM_FLOATS (XP_OFF + 4 * XP_STRIDE)

__global__ void __launch_bounds__(128, 3) maneuver_kernel(
    const float* __restrict__ nf,
    const int* __restrict__ gmask, const int* __restrict__ mm,
    const float* __restrict__ W1,
    const float* __restrict__ W2, const float* __restrict__ b2,
    float* __restrict__ out)
{
    extern __shared__ float sm[];
    float* sW1 = sm + SW1_OFF;
    const int tid  = threadIdx.x;
    const int w    = tid >> 5;
    const int lane = tid & 31;
    float* sxp = sm + XP_OFF + w * XP_STRIDE;

    // stage W1a (32KB) cooperatively: 2048 float4 / 128 threads
    {
        const float4* src = (const float4*)W1;
        float4* dst = (float4*)sW1;
        #pragma unroll
        for (int i = 0; i < 16; ++i) dst[tid + 128 * i] = src[tid + 128 * i];
    }

    const int b0 = blockIdx.x * 8 + w * 2;   // this warp owns batches b0, b0+1

    // ---- scan both batches: first <=8 selected nodes each ----
    int V[2];
    int my_node[2];
    #pragma unroll
    for (int bl = 0; bl < 2; ++bl) {
        const int b = b0 + bl;
        const int s = g_starts[b];
        const int e = g_starts[b + 1];
        int cnt = 0;
        my_node[bl] = -1;
        for (int base = s; base < e && cnt < 8; base += 32) {
            int i = base + lane;
            bool m = (i < e) && (gmask[i] != 0);
            unsigned bal = __ballot_sync(0xffffffffu, m);
            int ns = __popc(bal);
            int want = lane - cnt;
            if (lane < 8 && want >= 0 && want < ns) {
                unsigned mk = bal;
                #pragma unroll
                for (int t = 0; t < 7; ++t) if (t < want) mk &= (mk - 1u);
                my_node[bl] = base + (__ffs(mk) - 1);
            }
            cnt += ns;
        }
        V[bl] = cnt < 8 ? cnt : 8;
    }

    // ---- broadcast node indices, gather all 16 node rows (high MLP) ----
    int nidx[16];
    #pragma unroll
    for (int n = 0; n < 16; ++n)
        nidx[n] = __shfl_sync(0xffffffffu, my_node[n >> 3], n & 7);
    float a[16][4];
    #pragma unroll
    for (int n = 0; n < 16; ++n) {
        #pragma unroll
        for (int i = 0; i < 4; ++i)
            a[n][i] = (nidx[n] >= 0) ? nf[(size_t)nidx[n] * 128 + lane + 32 * i] : 0.f;
    }

    // gb for both batches (lane owns hidden 2l, 2l+1)
    float2 gv0 = *(const float2*)&g_gb[b0 * 64 + 2 * lane];
    float2 gv1 = *(const float2*)&g_gb[(b0 + 1) * 64 + 2 * lane];

    __syncthreads();   // W1a staged

    // ---- transpose store: per k, 8 node-pair float2s at stride-20 ----
    #pragma unroll
    for (int i = 0; i < 4; ++i) {
        int k = lane + 32 * i;
        #pragma unroll
        for (int p = 0; p < 8; ++p)
            *(float2*)&sxp[k * 20 + 2 * p] = make_float2(a[2 * p][i], a[2 * p + 1][i]);
    }
    __syncwarp();

    // ---- layer 1 mainloop: 16 nodes x 2 hidden per lane ----
    unsigned long long acc0[8], acc1[8];
    #pragma unroll
    for (int p = 0; p < 8; ++p) {
        float gx = (p < 4) ? gv0.x : gv1.x;
        float gy = (p < 4) ? gv0.y : gv1.y;
        acc0[p] = pk2(gx, gx);
        acc1[p] = pk2(gy, gy);
    }
    #pragma unroll 2
    for (int k = 0; k < 128; ++k) {
        float2 wv = *(const float2*)&sW1[k * 64 + 2 * lane];
        unsigned long long ww0 = pk2(wv.x, wv.x);
        unsigned long long ww1 = pk2(wv.y, wv.y);
        ulonglong2 xA = *(const ulonglong2*)&sxp[k * 20];        // b0 pairs 0,1
        ulonglong2 xB = *(const ulonglong2*)&sxp[k * 20 + 4];    // b0 pairs 2,3
        ulonglong2 xC = *(const ulonglong2*)&sxp[k * 20 + 8];    // b1 pairs 0,1
        ulonglong2 xD = *(const ulonglong2*)&sxp[k * 20 + 12];   // b1 pairs 2,3
        acc0[0] = fma2(xA.x, ww0, acc0[0]);  acc1[0] = fma2(xA.x, ww1, acc1[0]);
        acc0[1] = fma2(xA.y, ww0, acc0[1]);  acc1[1] = fma2(xA.y, ww1, acc1[1]);
        acc0[2] = fma2(xB.x, ww0, acc0[2]);  acc1[2] = fma2(xB.x, ww1, acc1[2]);
        acc0[3] = fma2(xB.y, ww0, acc0[3]);  acc1[3] = fma2(xB.y, ww1, acc1[3]);
        acc0[4] = fma2(xC.x, ww0, acc0[4]);  acc1[4] = fma2(xC.x, ww1, acc1[4]);
        acc0[5] = fma2(xC.y, ww0, acc0[5]);  acc1[5] = fma2(xC.y, ww1, acc1[5]);
        acc0[6] = fma2(xD.x, ww0, acc0[6]);  acc1[6] = fma2(xD.x, ww1, acc1[6]);
        acc0[7] = fma2(xD.y, ww0, acc0[7]);  acc1[7] = fma2(xD.y, ww1, acc1[7]);
    }

    // ---- relu, stash h (reuse sxp): h[n16*66 + j], n16 = bl*8 + n ----
    __syncwarp();
    #pragma unroll
    for (int p = 0; p < 8; ++p) {
        int n16 = (p >> 2) * 8 + (p & 3) * 2;   // first node of this pair
        float hx0, hy0, hx1, hy1;
        upk2(acc0[p], hx0, hy0);   // hidden 2l : node n16 (x), n16+1 (y)
        upk2(acc1[p], hx1, hy1);   // hidden 2l+1
        sxp[n16 * 66 + 2 * lane]           = fmaxf(hx0, 0.f);
        sxp[n16 * 66 + 2 * lane + 1]       = fmaxf(hx1, 0.f);
        sxp[(n16 + 1) * 66 + 2 * lane]     = fmaxf(hy0, 0.f);
        sxp[(n16 + 1) * 66 + 2 * lane + 1] = fmaxf(hy1, 0.f);
    }
    __syncwarp();

    // ---- layer 2 + mask + store: 112 outputs (2 batches x 56) ----
    #pragma unroll
    for (int p = 0; p < 4; ++p) {
        int idx = p * 32 + lane;
        if (idx < 112) {
            int bl = idx / 56;
            int r  = idx - bl * 56;
            int n  = r / 7, d = r - n * 7;
            int b  = b0 + bl;
            float val = NEGV;
            if (n < V[bl] && mm[b * 56 + r] != 0) {
                float sum = __ldg(&b2[d]);
                const float* hb = &sxp[(bl * 8 + n) * 66];
                #pragma unroll
                for (int j = 0; j < 64; ++j)
                    sum = fmaf(hb[j], __ldg(&W2[j * 7 + d]), sum);
                val = sum;
            }
            out[b * 56 + r] = val;
        }
    }
}

extern "C" void kernel_launch(void* const* d_in, const int* in_sizes, int n_in,
                              void* d_out, int out_size) {
    const float* nf    = (const float*)d_in[0];
    const float* glob  = (const float*)d_in[1];
    const int*   gmask = (const int*)d_in[2];
    const int*   batch = (const int*)d_in[3];
    const int*   mm    = (const int*)d_in[4];
    const float* W1    = (const float*)d_in[5];
    const float* b1    = (const float*)d_in[6];
    const float* W2    = (const float*)d_in[7];
    const float* b2    = (const float*)d_in[8];
    float*       out   = (float*)d_out;

    prep_kernel<<<768, 256>>>(batch, glob, W1, b1);

    size_t smem = (size_t)SMEM_FLOATS * sizeof(float);
    cudaFuncSetAttribute(maneuver_kernel,
                         cudaFuncAttributeMaxDynamicSharedMemorySize, (int)smem);
    maneuver_kernel<<<BB / 8, 128, smem>>>(nf, gmask, mm, W1, W2, b2, out);
}

// round 9
// speedup vs baseline: 1.1290x; 1.1290x over previous
#include <cuda_runtime.h>
#include <cuda_bf16.h>

#define NN 262144
#define BB 4096
#define NEGV -1000000000.0f

__device__ int g_starts[BB + 1];
__device__ float g_gb[BB * 64];   // precomputed glob@W1b + b1

// ---- fused prep: blocks [0,512) compute gb; blocks [512,768) compute seg starts ----
__global__ void __launch_bounds__(256) prep_kernel(
    const int* __restrict__ batch,
    const float* __restrict__ glob, const float* __restrict__ W1,
    const float* __restrict__ b1)
{
    const int tid = threadIdx.x, w = tid >> 5, lane = tid & 31;
    if (blockIdx.x < 512) {
        // gb[b][j] = glob[b] @ W1[128:][:,j] + b1[j]
        __shared__ float sW1b[8192];
        {
            const float4* src = (const float4*)(W1 + 128 * 64);
            float4* dst = (float4*)sW1b;
            #pragma unroll
            for (int i = 0; i < 8; ++i) dst[tid + 256 * i] = src[tid + 256 * i];
        }
        const int b = blockIdx.x * 8 + w;
        float gl[4];
        #pragma unroll
        for (int i = 0; i < 4; ++i) gl[i] = glob[b * 128 + lane + 32 * i];
        float2 bv = *(const float2*)&b1[2 * lane];
        float g0 = bv.x, g1 = bv.y;
        __syncthreads();
        #pragma unroll 8
        for (int k = 0; k < 128; ++k) {
            float x = __shfl_sync(0xffffffffu, gl[k >> 5], k & 31);
            float2 wv = *(const float2*)&sW1b[k * 64 + 2 * lane];
            g0 = fmaf(x, wv.x, g0);
            g1 = fmaf(x, wv.y, g1);
        }
        *(float2*)&g_gb[b * 64 + 2 * lane] = make_float2(g0, g1);
    } else {
        // segment starts, 4 elements per thread (int4)
        const int sid = blockIdx.x - 512;          // 0..255
        const int i0 = sid * 1024 + tid * 4;
        int4 v = *(const int4*)&batch[i0];
        int prev = __shfl_up_sync(0xffffffffu, v.w, 1);
        if (lane == 0) prev = (i0 == 0) ? -1 : batch[i0 - 1];
        int c[4] = {v.x, v.y, v.z, v.w};
        int p = prev;
        #pragma unroll
        for (int t = 0; t < 4; ++t) {
            for (int b = p + 1; b <= c[t]; ++b) g_starts[b] = i0 + t;
            p = c[t];
        }
        if (i0 + 4 == NN) {
            for (int b = v.w + 1; b <= BB; ++b) g_starts[b] = NN;
        }
    }
}

// ---- packed f32x2 helpers ----
__device__ __forceinline__ unsigned long long pk2(float a, float b) {
    unsigned long long r;
    asm("mov.b64 %0, {%1, %2};" : "=l"(r) : "f"(a), "f"(b));
    return r;
}
__device__ __forceinline__ void upk2(unsigned long long v, float& a, float& b) {
    asm("mov.b64 {%0, %1}, %2;" : "=f"(a), "=f"(b) : "l"(v));
}
__device__ __forceinline__ unsigned long long fma2(unsigned long long a,
                                                   unsigned long long b,
                                                   unsigned long long c) {
    unsigned long long r;
    asm("fma.rn.f32x2 %0, %1, %2, %3;" : "=l"(r) : "l"(a), "l"(b), "l"(c));
    return r;
}

// Main kernel: warp = batch. No staged weights (W1 via L1), 16KB static smem
// per CTA (per-warp xp transpose scratch, reused as h).
__global__ void __launch_bounds__(128, 7) maneuver_kernel(
    const float* __restrict__ nf,
    const int* __restrict__ gmask, const int* __restrict__ mm,
    const float* __restrict__ W1,
    const float* __restrict__ W2, const float* __restrict__ b2,
    float* __restrict__ out)
{
    __shared__ float sxp_all[4 * 1024];
    const int tid  = threadIdx.x;
    const int w    = tid >> 5;
    const int lane = tid & 31;
    float* sxp = sxp_all + w * 1024;   // 128 k x 8 floats

    const int b = blockIdx.x * 4 + w;
    const int s = g_starts[b];
    const int e = g_starts[b + 1];

    // gb early (independent LDG, overlaps scan)
    float2 gv = *(const float2*)&g_gb[b * 64 + 2 * lane];

    // ---- find first <=8 selected nodes in [s, e) ----
    int cnt = 0;
    int my_node = -1;   // lanes 0..7 each own one node index
    for (int base = s; base < e && cnt < 8; base += 32) {
        int i = base + lane;
        bool m = (i < e) && (gmask[i] != 0);
        unsigned bal = __ballot_sync(0xffffffffu, m);
        int ns = __popc(bal);
        int want = lane - cnt;
        if (lane < 8 && want >= 0 && want < ns) {
            unsigned mk = bal;
            #pragma unroll
            for (int t = 0; t < 7; ++t) if (t < want) mk &= (mk - 1u);
            my_node = base + (__ffs(mk) - 1);
        }
        cnt += ns;
    }
    const int V = cnt < 8 ? cnt : 8;

    // ---- gather 8 node rows as float4 (lane owns cols 4l..4l+3) ----
    const float4* nf4 = (const float4*)nf;
    float4 a[8];
    #pragma unroll
    for (int n = 0; n < 8; ++n) {
        int ni = __shfl_sync(0xffffffffu, my_node, n);
        a[n] = (ni >= 0) ? nf4[(size_t)ni * 32 + lane]
                         : make_float4(0.f, 0.f, 0.f, 0.f);
    }

    // ---- transpose to smem: k = 4*lane + j, 8 floats per k ----
    #pragma unroll
    for (int j = 0; j < 4; ++j) {
        int k = 4 * lane + j;
        float* p = &sxp[k * 8];
        ((float4*)p)[0] = make_float4(((const float*)&a[0])[j], ((const float*)&a[1])[j],
                                      ((const float*)&a[2])[j], ((const float*)&a[3])[j]);
        ((float4*)p)[1] = make_float4(((const float*)&a[4])[j], ((const float*)&a[5])[j],
                                      ((const float*)&a[6])[j], ((const float*)&a[7])[j]);
    }
    __syncwarp();

    // ---- layer 1 mainloop: 8 nodes x 2 hidden per lane, W1 via L1 ----
    unsigned long long acc0[4], acc1[4];
    #pragma unroll
    for (int p = 0; p < 4; ++p) {
        acc0[p] = pk2(gv.x, gv.x);
        acc1[p] = pk2(gv.y, gv.y);
    }
    const float2* W1v = (const float2*)W1;
    #pragma unroll 4
    for (int k = 0; k < 128; ++k) {
        float2 wv = __ldg(&W1v[k * 32 + lane]);
        unsigned long long ww0 = pk2(wv.x, wv.x);
        unsigned long long ww1 = pk2(wv.y, wv.y);
        ulonglong2 xA = *(const ulonglong2*)&sxp[k * 8];       // pairs 0,1
        ulonglong2 xB = *(const ulonglong2*)&sxp[k * 8 + 4];   // pairs 2,3
        acc0[0] = fma2(xA.x, ww0, acc0[0]);  acc1[0] = fma2(xA.x, ww1, acc1[0]);
        acc0[1] = fma2(xA.y, ww0, acc0[1]);  acc1[1] = fma2(xA.y, ww1, acc1[1]);
        acc0[2] = fma2(xB.x, ww0, acc0[2]);  acc1[2] = fma2(xB.x, ww1, acc1[2]);
        acc0[3] = fma2(xB.y, ww0, acc0[3]);  acc1[3] = fma2(xB.y, ww1, acc1[3]);
    }

    // ---- relu, stash h (reuse sxp): h[n*66 + j] ----
    __syncwarp();
    #pragma unroll
    for (int p = 0; p < 4; ++p) {
        float hx0, hy0, hx1, hy1;
        upk2(acc0[p], hx0, hy0);   // hidden 2l : node 2p (x), node 2p+1 (y)
        upk2(acc1[p], hx1, hy1);   // hidden 2l+1
        sxp[(2 * p) * 66 + 2 * lane]         = fmaxf(hx0, 0.f);
        sxp[(2 * p) * 66 + 2 * lane + 1]     = fmaxf(hx1, 0.f);
        sxp[(2 * p + 1) * 66 + 2 * lane]     = fmaxf(hy0, 0.f);
        sxp[(2 * p + 1) * 66 + 2 * lane + 1] = fmaxf(hy1, 0.f);
    }
    __syncwarp();

    // ---- layer 2 + mask + store: 56 outputs ----
    #pragma unroll
    for (int p = 0; p < 2; ++p) {
        int idx = p * 32 + lane;
        if (idx < 56) {
            int n = idx / 7, d = idx - n * 7;
            float val = NEGV;
            if (n < V && mm[b * 56 + idx] != 0) {
                float sum = __ldg(&b2[d]);
                const float* hb = &sxp[n * 66];
                #pragma unroll
                for (int j = 0; j < 64; ++j)
                    sum = fmaf(hb[j], __ldg(&W2[j * 7 + d]), sum);
                val = sum;
            }
            out[b * 56 + idx] = val;
        }
    }
}

extern "C" void kernel_launch(void* const* d_in, const int* in_sizes, int n_in,
                              void* d_out, int out_size) {
    const float* nf    = (const float*)d_in[0];
    const float* glob  = (const float*)d_in[1];
    const int*   gmask = (const int*)d_in[2];
    const int*   batch = (const int*)d_in[3];
    const int*   mm    = (const int*)d_in[4];
    const float* W1    = (const float*)d_in[5];
    const float* b1    = (const float*)d_in[6];
    const float* W2    = (const float*)d_in[7];
    const float* b2    = (const float*)d_in[8];
    float*       out   = (float*)d_out;

    prep_kernel<<<768, 256>>>(batch, glob, W1, b1);
    maneuver_kernel<<<BB / 4, 128>>>(nf, gmask, mm, W1, W2, b2, out);
}